// round 10
// baseline (speedup 1.0000x reference)
#include <cuda_runtime.h>
#include <cstdint>
#include <math.h>

#define Bq 128
#define Tq 512
#define Cq 100
#define Eq 64
#define Hq 256
#define KIN 320   // E+H

typedef unsigned long long ull;

// ---- scratch (device globals; no allocation in kernel_launch) ----
static __device__ float g_r[(size_t)Bq * Tq * Eq];          // rec_input
static __device__ __align__(16) float g_h[2][Bq][Hq];       // ping-pong h_d [buf][b][j]
static __device__ unsigned g_cnt[16];                       // [stream*8 + group]

__device__ __forceinline__ float sigmf_(float x) { return 1.f / (1.f + expf(-x)); }
__device__ __forceinline__ float softplusf_(float x) {
    return fmaxf(x, 0.f) + log1pf(expf(-fabsf(x)));
}
// fast variants (abs err ~1e-6, budget 1e-3)
__device__ __forceinline__ float sigf(float x) {
    return __fdividef(1.f, 1.f + __expf(-x));
}
__device__ __forceinline__ float tanf_(float x) {
    return 1.f - 2.f * __fdividef(1.f, 1.f + __expf(2.f * x));
}
__device__ __forceinline__ float splusf(float x) {
    return fmaxf(x, 0.f) + __logf(1.f + __expf(-fabsf(x)));
}
__device__ __forceinline__ void fma2_(ull& d, ull a, ull b) {
    asm volatile("fma.rn.f32x2 %0, %1, %2, %0;" : "+l"(d) : "l"(a), "l"(b));
}
__device__ __forceinline__ float lo_(ull v) { return __uint_as_float((unsigned)v); }
__device__ __forceinline__ float hi_(ull v) { return __uint_as_float((unsigned)(v >> 32)); }

// ---------------------------------------------------------------------------
// K1: rec_input[b,t,e] = (marks[b,t,:] @ W_emb[:,e]) / max(sum(marks),1)
// ---------------------------------------------------------------------------
__global__ __launch_bounds__(128) void k_embed(const float* __restrict__ marks,
                                               const float* __restrict__ Wemb) {
    int bt = blockIdx.x;
    __shared__ float sm[Cq];
    int tid = threadIdx.x;
    if (tid < Cq) sm[tid] = marks[(size_t)bt * Cq + tid];
    __syncthreads();
    if (tid < Eq) {
        float cnt = 0.f, s = 0.f;
        #pragma unroll
        for (int c = 0; c < Cq; c++) {
            float m = sm[c];
            cnt += m;
            s = fmaf(m, Wemb[c * Eq + tid], s);
        }
        g_r[(size_t)bt * Eq + tid] = s / fmaxf(cnt, 1.f);
    }
}

// ---------------------------------------------------------------------------
// K3: initial state -> out[b,0,:], g_h[0], reset sync counters
// ---------------------------------------------------------------------------
__global__ __launch_bounds__(256) void k_init(const float* __restrict__ init,
                                              float* __restrict__ out) {
    int b = blockIdx.x, k = threadIdx.x;
    if (b == 0 && k < 16) g_cnt[k] = 0;
    float s0 = init[k], s1 = init[Hq + k], s2 = init[2 * Hq + k];
    float s3 = init[3 * Hq + k], s4 = init[4 * Hq + k], s5 = init[5 * Hq + k];
    float hd0 = tanhf(s0), cd0 = tanhf(s1), cb0 = tanhf(s2), c0 = tanhf(s3);
    float d0 = softplusf_(s4), o0 = sigmf_(s5);
    size_t base = (size_t)b * (Tq + 1) * (6 * Hq);
    out[base + 0 * Hq + k] = hd0;
    out[base + 1 * Hq + k] = o0;
    out[base + 2 * Hq + k] = cb0;
    out[base + 3 * Hq + k] = c0;
    out[base + 4 * Hq + k] = d0;
    out[base + 5 * Hq + k] = cd0;
    g_h[0][b][k] = hd0;
}

// ---------------------------------------------------------------------------
// K4: fused recurrence, warp-specialized dual stream, ANTI-PHASED.
//   grid = 128 = 8 batch-groups (16 b) x 16 j-slices (16 j). 256 threads.
//   Warps 0-3 = stream A (b 0..7), warps 4-7 = stream B (b 8..15); SMSP i
//   hosts one A-warp and one B-warp. Stream B is skewed by ~half a step at
//   the prologue so B's GEMM overlaps A's sync/phase2 window and vice versa.
//   Per stream per t: stage regs->SMEM, bar, GEMM 7g x 4b x 80k (f32x2),
//   red STS, bar, phase2 (gates/decay/stcg h), bar, release, poll+prefetch
//   next h/r, THEN output STGs.
// ---------------------------------------------------------------------------
__global__ void __launch_bounds__(256, 1)
k_recur(const float* __restrict__ Wc, const float* __restrict__ ts,
        const float* __restrict__ init, const float* __restrict__ bc,
        float* __restrict__ out) {
    extern __shared__ float sh[];
    float* Ws  = sh;            // 28672: h-weights  ((g*64+kq)*16 + jw)*4 + e
    float* Wr  = sh + 28672;    //  7168: r-weights  ((g*16+rq)*16 + jw)*4 + e
    float* bs  = sh + 35840;    //   112: bias g*16+j   (+pad to 16B align)
    float* hs  = sh + 35952;    // 2*2048: staged h  float4 idx b*64 + kq
    float* rs  = sh + 40048;    // 2* 512: staged r  float4 idx b*16 + rq
    float* red = sh + 41072;    // 2*4480: partials  (s*7+g)*160 + b*20 + j

    int tid = threadIdx.x;
    int lane = tid & 31;
    int wid = tid >> 5;
    int stream = wid >> 2;           // 0: b 0..7, 1: b 8..15
    int s = wid & 3;                 // k-split 0..3
    int bg = lane >> 4, j1 = lane & 15;
    int bbase = bg * 4;
    int stid = tid & 127;            // stream-local tid
    int j2 = stid & 15, b2 = stid >> 4;

    int group = blockIdx.x >> 4;     // 0..7
    int rank  = blockIdx.x & 15;     // 0..15
    int j0 = rank * 16, jg = j0 + j2;
    int gb0 = group * 16 + stream * 8;
    int gbb = gb0 + b2;              // this thread's output batch
    unsigned* cnt = g_cnt + stream * 8 + group;
    int barid = stream + 1;

    float* hsS  = hs  + stream * 2048;
    float* rsS  = rs  + stream * 512;
    float* redS = red + stream * 4480;

    // one-time weight/bias loads (all 256 threads)
    for (int idx = tid; idx < 28672; idx += 256) {
        int e = idx & 3, jw = (idx >> 2) & 15, kq = (idx >> 6) & 63, g = idx >> 12;
        Ws[idx] = Wc[(size_t)(g * Hq + j0 + jw) * KIN + Eq + kq * 4 + e];
    }
    for (int idx = tid; idx < 7168; idx += 256) {
        int e = idx & 3, jw = (idx >> 2) & 15, rq = (idx >> 6) & 15, g = idx >> 10;
        Wr[idx] = Wc[(size_t)(g * Hq + j0 + jw) * KIN + rq * 4 + e];
    }
    if (tid < 112) bs[tid] = bc[(tid >> 4) * Hq + j0 + (tid & 15)];

    float c_st  = tanhf(init[3 * Hq + jg]);
    float cb_st = tanhf(init[2 * Hq + jg]);
    __syncthreads();   // last full-CTA barrier

    const ulonglong2* WU  = (const ulonglong2*)Ws;
    const ulonglong2* WrU = (const ulonglong2*)Wr;
    const ulonglong2* HU  = (const ulonglong2*)hsS;
    const ulonglong2* RU  = (const ulonglong2*)rsS;
    float4* hs4 = (float4*)hsS;
    float4* rs4 = (float4*)rsS;
    const float4* gr4 = (const float4*)g_r;

    // ---- anti-phase skew: stream B starts ~half a step late ----
    if (stream == 1) {
        long long t0 = clock64();
        while (clock64() - t0 < 2600) { }
    }

    // prefetch registers + prologue (t = 0)
    float4 ph[4], pr;
    float ptc, ptp = 0.f;
    {
        int bb = stid >> 6, kqq = stid & 63;   // bb 0..1
        const float4* gsrc = (const float4*)&g_h[0][0][0];
        #pragma unroll
        for (int i = 0; i < 4; i++)
            ph[i] = __ldcg(gsrc + (gb0 + bb + 2 * i) * 64 + kqq);
        pr  = gr4[((size_t)gbb * Tq + 0) * 16 + j2];
        ptc = ts[gbb * Tq + 0];
    }

    for (int t = 0; t < Tq; t++) {
        // ---- stage from prefetch regs ----
        {
            int bb = stid >> 6, kqq = stid & 63;
            #pragma unroll
            for (int i = 0; i < 4; i++)
                hs4[(bb + 2 * i) * 64 + kqq] = ph[i];
            rs4[stid] = pr;   // idx = b2*16 + j2
        }
        float tc = ptc, tp = ptp;
        asm volatile("bar.sync %0, 128;" :: "r"(barid) : "memory");

        // ---- GEMM: 7 g x 4 b, k-split s (80 k), packed f32x2 ----
        ull acc[7][4];
        #pragma unroll
        for (int g = 0; g < 7; g++)
            #pragma unroll
            for (int bi = 0; bi < 4; bi++) acc[g][bi] = 0ull;

        #pragma unroll
        for (int q = 0; q < 16; q++) {
            int kq = s * 16 + q;
            ulonglong2 hv[4];
            #pragma unroll
            for (int bi = 0; bi < 4; bi++)
                hv[bi] = HU[(bbase + bi) * 64 + kq];
            #pragma unroll
            for (int g = 0; g < 7; g++) {
                ulonglong2 wv = WU[(g * 64 + kq) * 16 + j1];
                #pragma unroll
                for (int bi = 0; bi < 4; bi++) {
                    fma2_(acc[g][bi], wv.x, hv[bi].x);
                    fma2_(acc[g][bi], wv.y, hv[bi].y);
                }
            }
        }
        #pragma unroll
        for (int q2 = 0; q2 < 4; q2++) {
            int rq = s * 4 + q2;
            ulonglong2 rv[4];
            #pragma unroll
            for (int bi = 0; bi < 4; bi++)
                rv[bi] = RU[(bbase + bi) * 16 + rq];
            #pragma unroll
            for (int g = 0; g < 7; g++) {
                ulonglong2 wv = WrU[(g * 16 + rq) * 16 + j1];
                #pragma unroll
                for (int bi = 0; bi < 4; bi++) {
                    fma2_(acc[g][bi], wv.x, rv[bi].x);
                    fma2_(acc[g][bi], wv.y, rv[bi].y);
                }
            }
        }

        // ---- store k-partials (conflict-free) ----
        #pragma unroll
        for (int g = 0; g < 7; g++)
            #pragma unroll
            for (int bi = 0; bi < 4; bi++)
                redS[(s * 7 + g) * 160 + (bbase + bi) * 20 + j1] =
                    lo_(acc[g][bi]) + hi_(acc[g][bi]);
        asm volatile("bar.sync %0, 128;" :: "r"(barid) : "memory");

        // ---- phase 2: reduce 4 partials + gates + decay ----
        float gate[7];
        #pragma unroll
        for (int g = 0; g < 7; g++) {
            float vv = bs[g * 16 + j2];
            #pragma unroll
            for (int sp = 0; sp < 4; sp++)
                vv += redS[(sp * 7 + g) * 160 + b2 * 20 + j2];
            gate[g] = vv;
        }
        float gi  = sigf(gate[0]);
        float gf  = sigf(gate[1]);
        float gz  = tanf_(gate[2]);
        float go  = sigf(gate[3]);
        float gib = sigf(gate[4]);
        float gfb = sigf(gate[5]);
        float gd  = splusf(gate[6]);
        float dt  = tc - tp;

        float ct  = gf * c_st + gi * gz;
        float cbt = gfb * cb_st + gib * gz;
        float cdt = cbt + (ct - cbt) * __expf(-gd * dt);
        float hdt = go * tanf_(cdt);

        c_st = ct; cb_st = cbt;
        __stcg(&g_h[(t & 1) ^ 1][gbb][jg], hdt);

        // ---- release: stream barrier orders all 128 stcg, then publish ----
        asm volatile("bar.sync %0, 128;" :: "r"(barid) : "memory");
        if (stid == 0)
            asm volatile("red.release.gpu.global.add.u32 [%0], %1;"
                         :: "l"(cnt), "r"(1u) : "memory");

        // ---- poll + prefetch FIRST (shortens release->discover path) ----
        if (t < Tq - 1) {
            unsigned target = 16u * (unsigned)(t + 1), v;
            do {
                asm volatile("ld.acquire.gpu.u32 %0, [%1];"
                             : "=r"(v) : "l"(cnt) : "memory");
            } while (v < target);

            int bb = stid >> 6, kqq = stid & 63;
            const float4* gsrc = (const float4*)&g_h[(t + 1) & 1][0][0];
            #pragma unroll
            for (int i = 0; i < 4; i++)
                ph[i] = __ldcg(gsrc + (gb0 + bb + 2 * i) * 64 + kqq);
            pr  = gr4[((size_t)gbb * Tq + t + 1) * 16 + j2];
            ptp = tc;
            ptc = ts[gbb * Tq + t + 1];
        }

        // ---- out writes last (pure sinks) ----
        size_t ob = ((size_t)gbb * (Tq + 1) + t + 1) * (size_t)(6 * Hq) + jg;
        __stcs(&out[ob + 0 * Hq], hdt);
        __stcs(&out[ob + 1 * Hq], go);
        __stcs(&out[ob + 2 * Hq], cbt);
        __stcs(&out[ob + 3 * Hq], ct);
        __stcs(&out[ob + 4 * Hq], gd);
        __stcs(&out[ob + 5 * Hq], cdt);
    }
}

// ---------------------------------------------------------------------------
extern "C" void kernel_launch(void* const* d_in, const int* in_sizes, int n_in,
                              void* d_out, int out_size) {
    const float* marks = (const float*)d_in[0];
    const float* ts    = (const float*)d_in[1];
    const float* Wemb  = (const float*)d_in[2];
    const float* Wc    = (const float*)d_in[3];
    const float* bc    = (const float*)d_in[4];
    const float* init  = (const float*)d_in[5];
    float* out = (float*)d_out;

    k_embed<<<Bq * Tq, 128>>>(marks, Wemb);
    k_init<<<Bq, 256>>>(init, out);

    const int SMEM = 50032 * (int)sizeof(float);   // 200,128 B
    cudaFuncSetAttribute(k_recur, cudaFuncAttributeMaxDynamicSharedMemorySize, SMEM);
    k_recur<<<128, 256, SMEM>>>(Wc, ts, init, bc, out);
}

// round 11
// speedup vs baseline: 1.0122x; 1.0122x over previous
#include <cuda_runtime.h>
#include <cstdint>
#include <math.h>

#define Bq 128
#define Tq 512
#define Cq 100
#define Eq 64
#define Hq 256
#define KIN 320   // E+H

typedef unsigned long long ull;

// ---- scratch (device globals; no allocation in kernel_launch) ----
static __device__ float g_r[(size_t)Bq * Tq * Eq];          // rec_input
static __device__ __align__(16) float g_h[2][Bq][Hq];       // ping-pong h_d [buf][b][j]
static __device__ unsigned g_cnt[16];                       // [stream*8 + group]

__device__ __forceinline__ float sigmf_(float x) { return 1.f / (1.f + expf(-x)); }
__device__ __forceinline__ float softplusf_(float x) {
    return fmaxf(x, 0.f) + log1pf(expf(-fabsf(x)));
}
// fast variants (abs err ~1e-6, budget 1e-3)
__device__ __forceinline__ float sigf(float x) {
    return __fdividef(1.f, 1.f + __expf(-x));
}
__device__ __forceinline__ float tanf_(float x) {
    return 1.f - 2.f * __fdividef(1.f, 1.f + __expf(2.f * x));
}
__device__ __forceinline__ float splusf(float x) {
    return fmaxf(x, 0.f) + __logf(1.f + __expf(-fabsf(x)));
}
__device__ __forceinline__ void fma2_(ull& d, ull a, ull b) {
    asm volatile("fma.rn.f32x2 %0, %1, %2, %0;" : "+l"(d) : "l"(a), "l"(b));
}
__device__ __forceinline__ float lo_(ull v) { return __uint_as_float((unsigned)v); }
__device__ __forceinline__ float hi_(ull v) { return __uint_as_float((unsigned)(v >> 32)); }

// ---------------------------------------------------------------------------
// K1: rec_input. 8 bt-rows per 256-thread block; Wemb staged in SMEM.
// ---------------------------------------------------------------------------
__global__ __launch_bounds__(256) void k_embed(const float* __restrict__ marks,
                                               const float* __restrict__ Wemb) {
    __shared__ float We[Cq * Eq];     // 6400 floats
    __shared__ float sm[8][Cq];
    int tid = threadIdx.x;
    int bt0 = blockIdx.x * 8;

    for (int idx = tid; idx < Cq * Eq; idx += 256) We[idx] = Wemb[idx];
    for (int idx = tid; idx < 8 * Cq; idx += 256) {
        int b = idx / Cq, c = idx % Cq;
        sm[b][c] = marks[(size_t)(bt0 + b) * Cq + c];
    }
    __syncthreads();

    int e = tid & 63, half = tid >> 6;    // half 0..3
    #pragma unroll
    for (int rep = 0; rep < 2; rep++) {
        int b = half + rep * 4;
        float cnt = 0.f, s = 0.f;
        #pragma unroll
        for (int c = 0; c < Cq; c++) {
            float m = sm[b][c];
            cnt += m;
            s = fmaf(m, We[c * Eq + e], s);
        }
        g_r[(size_t)(bt0 + b) * Eq + e] = s / fmaxf(cnt, 1.f);
    }
}

// ---------------------------------------------------------------------------
// K3: initial state -> out[b,0,:], g_h[0], reset sync counters
// ---------------------------------------------------------------------------
__global__ __launch_bounds__(256) void k_init(const float* __restrict__ init,
                                              float* __restrict__ out) {
    int b = blockIdx.x, k = threadIdx.x;
    if (b == 0 && k < 16) g_cnt[k] = 0;
    float s0 = init[k], s1 = init[Hq + k], s2 = init[2 * Hq + k];
    float s3 = init[3 * Hq + k], s4 = init[4 * Hq + k], s5 = init[5 * Hq + k];
    float hd0 = tanhf(s0), cd0 = tanhf(s1), cb0 = tanhf(s2), c0 = tanhf(s3);
    float d0 = softplusf_(s4), o0 = sigmf_(s5);
    size_t base = (size_t)b * (Tq + 1) * (6 * Hq);
    out[base + 0 * Hq + k] = hd0;
    out[base + 1 * Hq + k] = o0;
    out[base + 2 * Hq + k] = cb0;
    out[base + 3 * Hq + k] = c0;
    out[base + 4 * Hq + k] = d0;
    out[base + 5 * Hq + k] = cd0;
    g_h[0][b][k] = hd0;
}

// ---------------------------------------------------------------------------
// K4: fused recurrence, warp-specialized dual stream, crossbar-lean tiling.
//   grid = 128 = 8 batch-groups (16 b) x 16 j-slices (16 j). 256 threads.
//   Warps 0-3 = stream A (b 0..7), warps 4-7 = stream B (b 8..15).
//   Per stream (128 thr): stid = s*16 + j1 (s:8 k-split of 40, j1:16).
//   Thread tile 7 g x 8 b: each weight quad (16B) feeds 8 batches ->
//   w-LDS halved vs R9; crossbar ~4.1k < FMA floor 4480.
//   Per t: stage regs->SMEM, bar, GEMM (f32x2), red STS (conflict-free,
//   stride 144), bar, phase2 (1 out/thread), stcg h, bar, release,
//   out STGs, poll+prefetch next h/r.  (Exact R9 ordering.)
// ---------------------------------------------------------------------------
__global__ void __launch_bounds__(256, 1)
k_recur(const float* __restrict__ Wc, const float* __restrict__ ts,
        const float* __restrict__ init, const float* __restrict__ bc,
        float* __restrict__ out) {
    extern __shared__ float sh[];
    float* Ws  = sh;            // 28672: h-weights  ((g*64+kq)*16 + jw)*4 + e
    float* Wr  = sh + 28672;    //  7168: r-weights  ((g*16+rq)*16 + jw)*4 + e
    float* bs  = sh + 35840;    //   112 (+16 pad): bias g*16+j
    float* hs  = sh + 35968;    // 2*2048: staged h  float4 idx b*64 + kq
    float* rs  = sh + 40064;    // 2* 512: staged r  float4 idx b*16 + rq
    float* red = sh + 41088;    // 2*8064: partials  (g*8+b)*144 + s*16 + j

    int tid = threadIdx.x;
    int wid = tid >> 5;
    int stream = wid >> 2;           // 0: b 0..7, 1: b 8..15
    int stid = tid & 127;            // stream-local tid
    int s  = stid >> 4;              // k-split 0..7
    int j1 = stid & 15;
    int j2 = stid & 15, b2 = stid >> 4;   // phase-2: b2 0..7

    int group = blockIdx.x >> 4;     // 0..7
    int rank  = blockIdx.x & 15;     // 0..15
    int j0 = rank * 16, jg = j0 + j2;
    int gb0 = group * 16 + stream * 8;
    int gbb = gb0 + b2;              // this thread's output batch
    unsigned* cnt = g_cnt + stream * 8 + group;
    int barid = stream + 1;

    float* hsS  = hs  + stream * 2048;
    float* rsS  = rs  + stream * 512;
    float* redS = red + stream * 8064;

    // one-time weight/bias loads (all 256 threads)
    for (int idx = tid; idx < 28672; idx += 256) {
        int e = idx & 3, jw = (idx >> 2) & 15, kq = (idx >> 6) & 63, g = idx >> 12;
        Ws[idx] = Wc[(size_t)(g * Hq + j0 + jw) * KIN + Eq + kq * 4 + e];
    }
    for (int idx = tid; idx < 7168; idx += 256) {
        int e = idx & 3, jw = (idx >> 2) & 15, rq = (idx >> 6) & 15, g = idx >> 10;
        Wr[idx] = Wc[(size_t)(g * Hq + j0 + jw) * KIN + rq * 4 + e];
    }
    if (tid < 112) bs[tid] = bc[(tid >> 4) * Hq + j0 + (tid & 15)];

    float c_st  = tanhf(init[3 * Hq + jg]);
    float cb_st = tanhf(init[2 * Hq + jg]);
    __syncthreads();   // last full-CTA barrier

    const ulonglong2* WU  = (const ulonglong2*)Ws;
    const ulonglong2* WrU = (const ulonglong2*)Wr;
    const ulonglong2* HU  = (const ulonglong2*)hsS;
    const ulonglong2* RU  = (const ulonglong2*)rsS;
    float4* hs4 = (float4*)hsS;
    float4* rs4 = (float4*)rsS;
    const float4* gr4 = (const float4*)g_r;

    // prefetch registers + prologue (t = 0)
    float4 ph[4], pr;
    float ptc, ptp = 0.f;
    {
        int bb = stid >> 6, kqq = stid & 63;   // bb 0..1
        const float4* gsrc = (const float4*)&g_h[0][0][0];
        #pragma unroll
        for (int i = 0; i < 4; i++)
            ph[i] = __ldcg(gsrc + (gb0 + bb + 2 * i) * 64 + kqq);
        pr  = gr4[((size_t)gbb * Tq + 0) * 16 + j2];
        ptc = ts[gbb * Tq + 0];
    }

    for (int t = 0; t < Tq; t++) {
        // ---- stage from prefetch regs ----
        {
            int bb = stid >> 6, kqq = stid & 63;
            #pragma unroll
            for (int i = 0; i < 4; i++)
                hs4[(bb + 2 * i) * 64 + kqq] = ph[i];
            rs4[stid] = pr;   // idx = b2*16 + j2
        }
        float tc = ptc, tp = ptp;
        asm volatile("bar.sync %0, 128;" :: "r"(barid) : "memory");

        // ---- GEMM: 7 g x 8 b, k-split s (40 k), packed f32x2 ----
        ull acc[7][8];
        #pragma unroll
        for (int g = 0; g < 7; g++)
            #pragma unroll
            for (int bi = 0; bi < 8; bi++) acc[g][bi] = 0ull;

        #pragma unroll
        for (int q = 0; q < 8; q++) {
            int kq = s * 8 + q;
            ulonglong2 hv[8];
            #pragma unroll
            for (int bi = 0; bi < 8; bi++)
                hv[bi] = HU[bi * 64 + kq];
            #pragma unroll
            for (int g = 0; g < 7; g++) {
                ulonglong2 wv = WU[(g * 64 + kq) * 16 + j1];
                #pragma unroll
                for (int bi = 0; bi < 8; bi++) {
                    fma2_(acc[g][bi], wv.x, hv[bi].x);
                    fma2_(acc[g][bi], wv.y, hv[bi].y);
                }
            }
        }
        #pragma unroll
        for (int q2 = 0; q2 < 2; q2++) {
            int rq = s * 2 + q2;
            ulonglong2 rv[8];
            #pragma unroll
            for (int bi = 0; bi < 8; bi++)
                rv[bi] = RU[bi * 16 + rq];
            #pragma unroll
            for (int g = 0; g < 7; g++) {
                ulonglong2 wv = WrU[(g * 16 + rq) * 16 + j1];
                #pragma unroll
                for (int bi = 0; bi < 8; bi++) {
                    fma2_(acc[g][bi], wv.x, rv[bi].x);
                    fma2_(acc[g][bi], wv.y, rv[bi].y);
                }
            }
        }

        // ---- store k-partials (stride 144: s*16+j dense, b-halves disjoint) ----
        #pragma unroll
        for (int g = 0; g < 7; g++)
            #pragma unroll
            for (int bi = 0; bi < 8; bi++)
                redS[(g * 8 + bi) * 144 + s * 16 + j1] =
                    lo_(acc[g][bi]) + hi_(acc[g][bi]);
        asm volatile("bar.sync %0, 128;" :: "r"(barid) : "memory");

        // ---- phase 2: reduce 8 partials + gates + decay ----
        float gate[7];
        #pragma unroll
        for (int g = 0; g < 7; g++) {
            float vv = bs[g * 16 + j2];
            #pragma unroll
            for (int sp = 0; sp < 8; sp++)
                vv += redS[(g * 8 + b2) * 144 + sp * 16 + j2];
            gate[g] = vv;
        }
        float gi  = sigf(gate[0]);
        float gf  = sigf(gate[1]);
        float gz  = tanf_(gate[2]);
        float go  = sigf(gate[3]);
        float gib = sigf(gate[4]);
        float gfb = sigf(gate[5]);
        float gd  = splusf(gate[6]);
        float dt  = tc - tp;

        float ct  = gf * c_st + gi * gz;
        float cbt = gfb * cb_st + gib * gz;
        float cdt = cbt + (ct - cbt) * __expf(-gd * dt);
        float hdt = go * tanf_(cdt);

        c_st = ct; cb_st = cbt;
        __stcg(&g_h[(t & 1) ^ 1][gbb][jg], hdt);

        // ---- release: stream barrier orders all 128 stcg, then publish ----
        asm volatile("bar.sync %0, 128;" :: "r"(barid) : "memory");
        if (stid == 0)
            asm volatile("red.release.gpu.global.add.u32 [%0], %1;"
                         :: "l"(cnt), "r"(1u) : "memory");

        // ---- out writes AFTER release ----
        size_t ob = ((size_t)gbb * (Tq + 1) + t + 1) * (size_t)(6 * Hq) + jg;
        __stcs(&out[ob + 0 * Hq], hdt);
        __stcs(&out[ob + 1 * Hq], go);
        __stcs(&out[ob + 2 * Hq], cbt);
        __stcs(&out[ob + 3 * Hq], ct);
        __stcs(&out[ob + 4 * Hq], gd);
        __stcs(&out[ob + 5 * Hq], cdt);

        // ---- prefetch next step's h/r (poll + ldcg) ----
        if (t < Tq - 1) {
            unsigned target = 16u * (unsigned)(t + 1), v;
            do {
                asm volatile("ld.acquire.gpu.u32 %0, [%1];"
                             : "=r"(v) : "l"(cnt) : "memory");
            } while (v < target);

            int bb = stid >> 6, kqq = stid & 63;
            const float4* gsrc = (const float4*)&g_h[(t + 1) & 1][0][0];
            #pragma unroll
            for (int i = 0; i < 4; i++)
                ph[i] = __ldcg(gsrc + (gb0 + bb + 2 * i) * 64 + kqq);
            pr  = gr4[((size_t)gbb * Tq + t + 1) * 16 + j2];
            ptp = tc;
            ptc = ts[gbb * Tq + t + 1];
        }
    }
}

// ---------------------------------------------------------------------------
extern "C" void kernel_launch(void* const* d_in, const int* in_sizes, int n_in,
                              void* d_out, int out_size) {
    const float* marks = (const float*)d_in[0];
    const float* ts    = (const float*)d_in[1];
    const float* Wemb  = (const float*)d_in[2];
    const float* Wc    = (const float*)d_in[3];
    const float* bc    = (const float*)d_in[4];
    const float* init  = (const float*)d_in[5];
    float* out = (float*)d_out;

    k_embed<<<(Bq * Tq) / 8, 256>>>(marks, Wemb);
    k_init<<<Bq, 256>>>(init, out);

    const int SMEM = 57216 * (int)sizeof(float);   // 228,864 B
    cudaFuncSetAttribute(k_recur, cudaFuncAttributeMaxDynamicSharedMemorySize, SMEM);
    k_recur<<<128, 256, SMEM>>>(Wc, ts, init, bc, out);
}